// round 6
// baseline (speedup 1.0000x reference)
#include <cuda_runtime.h>

#define BB 8
#define NN 1024
#define CC 64
#define OO 64
#define KK 4           // K+1 Chebyshev terms
#define EPS30 1e-30f

// Scratch (static __device__ arrays: allocation-free, tiny)
__device__ __align__(16) float2 g_si[BB*NN];     // (sR_i + b_r, sI_i + b_i)
__device__ __align__(16) float2 g_sj[BB*NN];     // (sR_j, sI_j)
__device__ __align__(16) float  g_rinv[BB*NN];   // 1 / sum_i exp(mag)
__device__ float g_rowR[BB*KK*NN];
__device__ float g_rowI[BB*KK*NN];

// ---------------------------------------------------------------------------
// K1: attention score vectors. One warp per (b,n) row; lanes split C=64.
// ---------------------------------------------------------------------------
__global__ void k1_svec(const float* __restrict__ Xr, const float* __restrict__ Xi,
                        const float* __restrict__ awr, const float* __restrict__ awi,
                        const float* __restrict__ abr, const float* __restrict__ abi)
{
    int gw   = (blockIdx.x * blockDim.x + threadIdx.x) >> 5;
    int lane = threadIdx.x & 31;
    if (gw >= BB*NN) return;
    const float* xr = Xr + gw*CC;
    const float* xi = Xi + gw*CC;
    float sRi=0.f, sIi=0.f, sRj=0.f, sIj=0.f;
#pragma unroll
    for (int t = 0; t < 2; ++t) {
        int c = lane + 32*t;
        float xrv = __ldg(xr + c), xiv = __ldg(xi + c);
        float wri = __ldg(awr + c), wrj = __ldg(awr + c + CC);
        float wii = __ldg(awi + c), wij = __ldg(awi + c + CC);
        sRi += xrv*wri - xiv*wii;
        sIi += xrv*wii + xiv*wri;
        sRj += xrv*wrj - xiv*wij;
        sIj += xrv*wij + xiv*wrj;
    }
#pragma unroll
    for (int off = 16; off; off >>= 1) {
        sRi += __shfl_xor_sync(0xffffffffu, sRi, off);
        sIi += __shfl_xor_sync(0xffffffffu, sIi, off);
        sRj += __shfl_xor_sync(0xffffffffu, sRj, off);
        sIj += __shfl_xor_sync(0xffffffffu, sIj, off);
    }
    if (lane == 0) {
        g_si[gw] = make_float2(sRi + abr[0], sIi + abi[0]);   // fold bias once (into s_i)
        g_sj[gw] = make_float2(sRj, sIj);
    }
}

// ---------------------------------------------------------------------------
// K2: softmax denominators per (b,j): sum over i of exp(mag(i,j)).
// Block = (b, 32 j's); 8 i-groups of 128 i each; s_i cached in smem.
// ---------------------------------------------------------------------------
__global__ __launch_bounds__(256) void k2_colsum(const float* __restrict__ par,
                                                 const float* __restrict__ pai)
{
    __shared__ float2 s_si[NN];
    __shared__ float  red[8][32];
    int b     = blockIdx.y;
    int jbase = blockIdx.x * 32;
    int tid   = threadIdx.x;
    int jl = tid & 31, ig = tid >> 5;
    for (int idx = tid; idx < NN; idx += 256) s_si[idx] = g_si[b*NN + idx];
    __syncthreads();
    float a_r = par[0], a_i = pai[0];
    float2 sj = g_sj[b*NN + jbase + jl];
    float esum = 0.f;
#pragma unroll 4
    for (int ii = 0; ii < 128; ++ii) {
        float2 si = s_si[ig*128 + ii];
        float scr = si.x + sj.x, sci = si.y + sj.y;
        float pr = fmaxf(scr, a_r*scr);         // PReLU (a<1)
        float pi = fmaxf(sci, a_i*sci);
        float mag2 = fmaf(pr, pr, fmaf(pi, pi, EPS30));
        float rim  = rsqrtf(mag2);              // MUFU.RSQ
        float e    = __expf(mag2*rim);          // exp(mag), no max-sub needed (mag<~5)
        esum += e;
    }
    red[ig][jl] = esum;
    __syncthreads();
    if (tid < 32) {
        float tot = 0.f;
#pragma unroll
        for (int g = 0; g < 8; ++g) tot += red[g][tid];
        g_rinv[b*NN + jbase + tid] = 1.0f / tot;
    }
}

// ---------------------------------------------------------------------------
// K3: the 256MB streamer. Block per (b,i); thread handles 4 consecutive j.
// Recomputes ar/ai on the fly (FMA+MUFU hidden under DRAM latency), does the
// complex Hadamard + row-sum over j for all 4 Chebyshev terms.
// ---------------------------------------------------------------------------
__global__ __launch_bounds__(256) void k3_row(const float* __restrict__ Lr,
                                              const float* __restrict__ Li,
                                              const float* __restrict__ par,
                                              const float* __restrict__ pai)
{
    __shared__ float sred[8][8];
    int bi  = blockIdx.x;               // b*1024 + i
    int b   = bi >> 10, i = bi & (NN-1);
    int tid = threadIdx.x;
    int j0  = tid << 2;
    float a_r = par[0], a_i = pai[0];
    float2 si = g_si[bi];
    const float4* sjp = reinterpret_cast<const float4*>(g_sj + b*NN + j0);
    float4 sjA = __ldg(sjp), sjB = __ldg(sjp + 1);
    float4 rv4 = __ldg(reinterpret_cast<const float4*>(g_rinv + b*NN + j0));
    float sjr[4] = {sjA.x, sjA.z, sjB.x, sjB.z};
    float sji[4] = {sjA.y, sjA.w, sjB.y, sjB.w};
    float rvv[4] = {rv4.x, rv4.y, rv4.z, rv4.w};
    float tr[4], ur[4];
#pragma unroll
    for (int j = 0; j < 4; ++j) {
        float scr = si.x + sjr[j], sci = si.y + sji[j];
        float pr = fmaxf(scr, a_r*scr);
        float pi = fmaxf(sci, a_i*sci);
        float mag2 = fmaf(pr, pr, fmaf(pi, pi, EPS30));
        float rim  = rsqrtf(mag2);
        float e    = __expf(mag2*rim);
        float w    = e * rim * rvv[j];  // softmax/(mag+eps): rsqrt replaces rcp
        tr[j] = pr * w;                 // = ar
        ur[j] = pi * w;                 // = ai
    }
    size_t base = ((size_t)(b*KK)*NN + i)*NN + j0;
    const float4* lrp = reinterpret_cast<const float4*>(Lr + base);
    const float4* lip = reinterpret_cast<const float4*>(Li + base);
    const int kstride = NN*NN/4;
    float accR[KK], accI[KK];
#pragma unroll
    for (int k = 0; k < KK; ++k) {
        float4 L4 = __ldg(lrp + k*kstride);
        float4 M4 = __ldg(lip + k*kstride);
        float aR, aI;
        aR  = L4.x*tr[0] - M4.x*ur[0];
        aI  = L4.x*ur[0] + M4.x*tr[0];
        aR += L4.y*tr[1] - M4.y*ur[1];
        aI += L4.y*ur[1] + M4.y*tr[1];
        aR += L4.z*tr[2] - M4.z*ur[2];
        aI += L4.z*ur[2] + M4.z*tr[2];
        aR += L4.w*tr[3] - M4.w*ur[3];
        aI += L4.w*ur[3] + M4.w*tr[3];
        accR[k] = aR; accI[k] = aI;
    }
#pragma unroll
    for (int off = 16; off; off >>= 1) {
#pragma unroll
        for (int k = 0; k < KK; ++k) {
            accR[k] += __shfl_xor_sync(0xffffffffu, accR[k], off);
            accI[k] += __shfl_xor_sync(0xffffffffu, accI[k], off);
        }
    }
    int warp = tid >> 5, lane = tid & 31;
    if (lane == 0) {
#pragma unroll
        for (int k = 0; k < KK; ++k) { sred[warp][k] = accR[k]; sred[warp][k+4] = accI[k]; }
    }
    __syncthreads();
    if (tid < 8) {
        float s = 0.f;
#pragma unroll
        for (int w = 0; w < 8; ++w) s += sred[w][tid];
        if (tid < 4) g_rowR[(b*KK + tid    )*NN + i] = s;
        else         g_rowI[(b*KK + tid - 4)*NN + i] = s;
    }
}

// ---------------------------------------------------------------------------
// K4: fused output einsums. Block per (b, 64-j tile); per m: P=Xr@wr, Q=Xi@wi
// register tiles (4x4/thread), combined with rowR/rowI. c split in 2 chunks
// to keep static smem < 48KB.
// ---------------------------------------------------------------------------
__global__ __launch_bounds__(256) void k4_out(const float* __restrict__ Xr,
                                              const float* __restrict__ Xi,
                                              const float* __restrict__ wr,
                                              const float* __restrict__ wi,
                                              float* __restrict__ out)
{
    __shared__ __align__(16) float xrT[32][68];  // [c][j], padded
    __shared__ __align__(16) float xiT[32][68];
    __shared__ __align__(16) float wrs[32][64];  // [c][o]
    __shared__ __align__(16) float wis[32][64];
    int b     = blockIdx.y;
    int jbase = blockIdx.x * 64;
    int tid   = threadIdx.x;
    int to = tid & 15, tj = tid >> 4;            // o = to*4+oo, j = jbase+tj*4+jj
    float accRe[4][4] = {}, accIm[4][4] = {};
#pragma unroll 1
    for (int m = 0; m < KK; ++m) {
        float rR[4], rI[4];
#pragma unroll
        for (int jj = 0; jj < 4; ++jj) {
            int jg = jbase + tj*4 + jj;
            rR[jj] = g_rowR[(b*KK + m)*NN + jg];
            rI[jj] = g_rowI[(b*KK + m)*NN + jg];
        }
        float p[4][4] = {}, q[4][4] = {};
#pragma unroll 1
        for (int ch = 0; ch < 2; ++ch) {
            __syncthreads();
            for (int idx = tid; idx < 64*32; idx += 256) {   // X chunk, transposed
                int cl = idx & 31, jl = idx >> 5;
                xrT[cl][jl] = Xr[(b*NN + jbase + jl)*CC + ch*32 + cl];
                xiT[cl][jl] = Xi[(b*NN + jbase + jl)*CC + ch*32 + cl];
            }
            for (int idx = tid; idx < 32*64; idx += 256) {   // w chunk
                int o = idx & 63, cl = idx >> 6;
                wrs[cl][o] = wr[m*CC*OO + (ch*32 + cl)*OO + o];
                wis[cl][o] = wi[m*CC*OO + (ch*32 + cl)*OO + o];
            }
            __syncthreads();
#pragma unroll 8
            for (int c = 0; c < 32; ++c) {
                float4 x4 = *reinterpret_cast<const float4*>(&xrT[c][tj*4]);
                float4 y4 = *reinterpret_cast<const float4*>(&xiT[c][tj*4]);
                float4 wv = *reinterpret_cast<const float4*>(&wrs[c][to*4]);
                float4 zv = *reinterpret_cast<const float4*>(&wis[c][to*4]);
                float xa[4] = {x4.x,x4.y,x4.z,x4.w};
                float ya[4] = {y4.x,y4.y,y4.z,y4.w};
                float wa[4] = {wv.x,wv.y,wv.z,wv.w};
                float za[4] = {zv.x,zv.y,zv.z,zv.w};
#pragma unroll
                for (int jj = 0; jj < 4; ++jj)
#pragma unroll
                    for (int oo = 0; oo < 4; ++oo) {
                        p[jj][oo] = fmaf(xa[jj], wa[oo], p[jj][oo]);
                        q[jj][oo] = fmaf(ya[jj], za[oo], q[jj][oo]);
                    }
            }
        }
#pragma unroll
        for (int jj = 0; jj < 4; ++jj)
#pragma unroll
            for (int oo = 0; oo < 4; ++oo) {
                accRe[jj][oo] += rR[jj]*p[jj][oo] - rI[jj]*q[jj][oo];
                accIm[jj][oo] += rI[jj]*p[jj][oo] + rR[jj]*q[jj][oo];
            }
    }
    const int imag_off = BB*NN*OO;
#pragma unroll
    for (int jj = 0; jj < 4; ++jj) {
        int jg = jbase + tj*4 + jj;
        float4 re4 = make_float4(accRe[jj][0], accRe[jj][1], accRe[jj][2], accRe[jj][3]);
        float4 im4 = make_float4(accIm[jj][0], accIm[jj][1], accIm[jj][2], accIm[jj][3]);
        *reinterpret_cast<float4*>(out + (size_t)(b*NN + jg)*OO + to*4) = re4;
        *reinterpret_cast<float4*>(out + imag_off + (size_t)(b*NN + jg)*OO + to*4) = im4;
    }
}

// ---------------------------------------------------------------------------
extern "C" void kernel_launch(void* const* d_in, const int* in_sizes, int n_in,
                              void* d_out, int out_size)
{
    const float* Xr  = (const float*)d_in[0];
    const float* Xi  = (const float*)d_in[1];
    const float* Lr  = (const float*)d_in[2];
    const float* Li  = (const float*)d_in[3];
    const float* wr  = (const float*)d_in[4];
    const float* wi  = (const float*)d_in[5];
    const float* awr = (const float*)d_in[6];
    const float* awi = (const float*)d_in[7];
    const float* abr = (const float*)d_in[8];
    const float* abi = (const float*)d_in[9];
    const float* par = (const float*)d_in[10];
    const float* pai = (const float*)d_in[11];
    float* out = (float*)d_out;

    k1_svec  <<<BB*NN/8, 256>>>(Xr, Xi, awr, awi, abr, abi);
    k2_colsum<<<dim3(NN/32, BB), 256>>>(par, pai);
    k3_row   <<<BB*NN, 256>>>(Lr, Li, par, pai);
    k4_out   <<<dim3(NN/64, BB), 256>>>(Xr, Xi, wr, wi, out);
}

// round 8
// speedup vs baseline: 1.4117x; 1.4117x over previous
#include <cuda_runtime.h>

#define BB 8
#define NN 1024
#define CC 64
#define OO 64
#define KK 4           // K+1 Chebyshev terms
#define EPS30 1e-30f

// Scratch (static __device__ arrays: allocation-free, tiny)
__device__ __align__(16) float2 g_si[BB*NN];     // (sR_i + b_r, sI_i + b_i)
__device__ __align__(16) float2 g_sj[BB*NN];     // (sR_j, sI_j)
__device__ __align__(16) float  g_rinv[BB*NN];   // 1 / sum_i exp(mag)
__device__ float g_rowR[BB*KK*NN];
__device__ float g_rowI[BB*KK*NN];

// ---------------------------------------------------------------------------
// K1: attention score vectors. One warp per (b,n) row; lanes split C=64.
// ---------------------------------------------------------------------------
__global__ void k1_svec(const float* __restrict__ Xr, const float* __restrict__ Xi,
                        const float* __restrict__ awr, const float* __restrict__ awi,
                        const float* __restrict__ abr, const float* __restrict__ abi)
{
    int gw   = (blockIdx.x * blockDim.x + threadIdx.x) >> 5;
    int lane = threadIdx.x & 31;
    if (gw >= BB*NN) return;
    const float* xr = Xr + gw*CC;
    const float* xi = Xi + gw*CC;
    float sRi=0.f, sIi=0.f, sRj=0.f, sIj=0.f;
#pragma unroll
    for (int t = 0; t < 2; ++t) {
        int c = lane + 32*t;
        float xrv = __ldg(xr + c), xiv = __ldg(xi + c);
        float wri = __ldg(awr + c), wrj = __ldg(awr + c + CC);
        float wii = __ldg(awi + c), wij = __ldg(awi + c + CC);
        sRi += xrv*wri - xiv*wii;
        sIi += xrv*wii + xiv*wri;
        sRj += xrv*wrj - xiv*wij;
        sIj += xrv*wij + xiv*wrj;
    }
#pragma unroll
    for (int off = 16; off; off >>= 1) {
        sRi += __shfl_xor_sync(0xffffffffu, sRi, off);
        sIi += __shfl_xor_sync(0xffffffffu, sIi, off);
        sRj += __shfl_xor_sync(0xffffffffu, sRj, off);
        sIj += __shfl_xor_sync(0xffffffffu, sIj, off);
    }
    if (lane == 0) {
        g_si[gw] = make_float2(sRi + abr[0], sIi + abi[0]);   // fold bias once
        g_sj[gw] = make_float2(sRj, sIj);
    }
}

// ---------------------------------------------------------------------------
// K2: softmax denominators per (b,j): sum over i of exp(mag(i,j)).
// ---------------------------------------------------------------------------
__global__ __launch_bounds__(256) void k2_colsum(const float* __restrict__ par,
                                                 const float* __restrict__ pai)
{
    __shared__ float2 s_si[NN];
    __shared__ float  red[8][32];
    int b     = blockIdx.y;
    int jbase = blockIdx.x * 32;
    int tid   = threadIdx.x;
    int jl = tid & 31, ig = tid >> 5;
    for (int idx = tid; idx < NN; idx += 256) s_si[idx] = g_si[b*NN + idx];
    __syncthreads();
    float a_r = par[0], a_i = pai[0];
    float2 sj = g_sj[b*NN + jbase + jl];
    float esum = 0.f;
#pragma unroll 4
    for (int ii = 0; ii < 128; ++ii) {
        float2 si = s_si[ig*128 + ii];
        float scr = si.x + sj.x, sci = si.y + sj.y;
        float pr = fmaxf(scr, a_r*scr);         // PReLU (a<1)
        float pi = fmaxf(sci, a_i*sci);
        float mag2 = fmaf(pr, pr, fmaf(pi, pi, EPS30));
        float rim  = rsqrtf(mag2);
        float e    = __expf(mag2*rim);          // exp(mag)
        esum += e;
    }
    red[ig][jl] = esum;
    __syncthreads();
    if (tid < 32) {
        float tot = 0.f;
#pragma unroll
        for (int g = 0; g < 8; ++g) tot += red[g][tid];
        g_rinv[b*NN + jbase + tid] = 1.0f / tot;
    }
}

// ---------------------------------------------------------------------------
// K3: 256MB streamer — WARP PER (b,i) ROW. Each warp sweeps all 1024 j in 8
// chunks of float4; only reduction is one warp butterfly at the end.
// All 8 L/M loads per chunk issued before the weight math (MLP=8).
// ---------------------------------------------------------------------------
__global__ __launch_bounds__(256) void k3_row(const float* __restrict__ Lr,
                                              const float* __restrict__ Li,
                                              const float* __restrict__ par,
                                              const float* __restrict__ pai)
{
    int warp = threadIdx.x >> 5, lane = threadIdx.x & 31;
    int bi = blockIdx.x * 8 + warp;          // 8 rows per block, same b per block
    int b  = bi >> 10, i = bi & (NN-1);
    float a_r = par[0], a_i = pai[0];
    float2 si = g_si[bi];
    const float* LrB = Lr + ((size_t)(b*KK)*NN + i)*NN;
    const float* LiB = Li + ((size_t)(b*KK)*NN + i)*NN;
    const size_t ks = (size_t)NN*NN;
    float accR[KK] = {}, accI[KK] = {};
#pragma unroll
    for (int ch = 0; ch < 8; ++ch) {
        int j0 = ch*128 + lane*4;
        // batch all DRAM loads first
        float4 L[KK], M[KK];
#pragma unroll
        for (int k = 0; k < KK; ++k) {
            L[k] = __ldg(reinterpret_cast<const float4*>(LrB + k*ks + j0));
            M[k] = __ldg(reinterpret_cast<const float4*>(LiB + k*ks + j0));
        }
        float4 sjA = __ldg(reinterpret_cast<const float4*>(g_sj + b*NN + j0));
        float4 sjB = __ldg(reinterpret_cast<const float4*>(g_sj + b*NN + j0) + 1);
        float4 rv4 = __ldg(reinterpret_cast<const float4*>(g_rinv + b*NN + j0));
        float sjr[4] = {sjA.x, sjA.z, sjB.x, sjB.z};
        float sji[4] = {sjA.y, sjA.w, sjB.y, sjB.w};
        float rvv[4] = {rv4.x, rv4.y, rv4.z, rv4.w};
        float tr[4], ur[4];
#pragma unroll
        for (int j = 0; j < 4; ++j) {
            float scr = si.x + sjr[j], sci = si.y + sji[j];
            float pr = fmaxf(scr, a_r*scr);
            float pi = fmaxf(sci, a_i*sci);
            float mag2 = fmaf(pr, pr, fmaf(pi, pi, EPS30));
            float rim  = rsqrtf(mag2);
            float e    = __expf(mag2*rim);
            float w    = e * rim * rvv[j];   // softmax/(mag+eps) via rsqrt
            tr[j] = pr * w;                  // = ar
            ur[j] = pi * w;                  // = ai
        }
#pragma unroll
        for (int k = 0; k < KK; ++k) {
            float aR, aI;
            aR  = L[k].x*tr[0] - M[k].x*ur[0];
            aI  = L[k].x*ur[0] + M[k].x*tr[0];
            aR += L[k].y*tr[1] - M[k].y*ur[1];
            aI += L[k].y*ur[1] + M[k].y*tr[1];
            aR += L[k].z*tr[2] - M[k].z*ur[2];
            aI += L[k].z*ur[2] + M[k].z*tr[2];
            aR += L[k].w*tr[3] - M[k].w*ur[3];
            aI += L[k].w*ur[3] + M[k].w*tr[3];
            accR[k] += aR; accI[k] += aI;
        }
    }
#pragma unroll
    for (int off = 16; off; off >>= 1) {
#pragma unroll
        for (int k = 0; k < KK; ++k) {
            accR[k] += __shfl_xor_sync(0xffffffffu, accR[k], off);
            accI[k] += __shfl_xor_sync(0xffffffffu, accI[k], off);
        }
    }
    if (lane == 0) {
#pragma unroll
        for (int k = 0; k < KK; ++k) {
            g_rowR[(b*KK + k)*NN + i] = accR[k];
            g_rowI[(b*KK + k)*NN + i] = accI[k];
        }
    }
}

// ---------------------------------------------------------------------------
// K4: fused output einsums. 512-thread blocks: two 256-thread halves split the
// m-loop (half 0: m=0,1; half 1: m=2,3), combined once via smem at the end.
// X tile hoisted into dynamic smem ONCE per block; each half has its own w slab.
// Dynamic smem layout (floats): xrT[64][68] | xiT[64][68] | wrs[2][64][64] | wis[2][64][64]
// ---------------------------------------------------------------------------
#define K4_XR 0
#define K4_XI 4352
#define K4_WR 8704
#define K4_WI 16896
#define K4_SMEM_BYTES (25088*4)

__global__ __launch_bounds__(512) void k4_out(const float* __restrict__ Xr,
                                              const float* __restrict__ Xi,
                                              const float* __restrict__ wr,
                                              const float* __restrict__ wi,
                                              float* __restrict__ out)
{
    extern __shared__ float sm[];
    float* xrT = sm + K4_XR;
    float* xiT = sm + K4_XI;
    float* wrs = sm + K4_WR;
    float* wis = sm + K4_WI;

    int b     = blockIdx.y;
    int jbase = blockIdx.x * 64;
    int tid   = threadIdx.x;
    int half  = tid >> 8;           // 0: m=0,1   1: m=2,3
    int wt    = tid & 255;
    int to = wt & 15, tj = wt >> 4; // o = to*4+oo, j = jbase+tj*4+jj

    // Load X tile once (transposed [c][j])
    for (int idx = tid; idx < CC*64; idx += 512) {
        int cl = idx & 63, jl = idx >> 6;
        xrT[cl*68 + jl] = Xr[(b*NN + jbase + jl)*CC + cl];
        xiT[cl*68 + jl] = Xi[(b*NN + jbase + jl)*CC + cl];
    }

    float accRe[4][4] = {}, accIm[4][4] = {};
#pragma unroll 1
    for (int mi = 0; mi < 2; ++mi) {
        int m = half*2 + mi;
        __syncthreads();                         // X ready / prev w reads done
        for (int idx = wt; idx < CC*OO; idx += 256) {
            wrs[half*4096 + idx] = wr[m*CC*OO + idx];
            wis[half*4096 + idx] = wi[m*CC*OO + idx];
        }
        __syncthreads();
        float rR[4], rI[4];
#pragma unroll
        for (int jj = 0; jj < 4; ++jj) {
            int jg = jbase + tj*4 + jj;
            rR[jj] = g_rowR[(b*KK + m)*NN + jg];
            rI[jj] = g_rowI[(b*KK + m)*NN + jg];
        }
        float p[4][4] = {}, q[4][4] = {};
#pragma unroll 8
        for (int c = 0; c < CC; ++c) {
            float4 x4 = *reinterpret_cast<const float4*>(&xrT[c*68 + tj*4]);
            float4 y4 = *reinterpret_cast<const float4*>(&xiT[c*68 + tj*4]);
            float4 wv = *reinterpret_cast<const float4*>(&wrs[half*4096 + c*64 + to*4]);
            float4 zv = *reinterpret_cast<const float4*>(&wis[half*4096 + c*64 + to*4]);
            float xa[4] = {x4.x,x4.y,x4.z,x4.w};
            float ya[4] = {y4.x,y4.y,y4.z,y4.w};
            float wa[4] = {wv.x,wv.y,wv.z,wv.w};
            float za[4] = {zv.x,zv.y,zv.z,zv.w};
#pragma unroll
            for (int jj = 0; jj < 4; ++jj)
#pragma unroll
                for (int oo = 0; oo < 4; ++oo) {
                    p[jj][oo] = fmaf(xa[jj], wa[oo], p[jj][oo]);
                    q[jj][oo] = fmaf(ya[jj], za[oo], q[jj][oo]);
                }
        }
#pragma unroll
        for (int jj = 0; jj < 4; ++jj)
#pragma unroll
            for (int oo = 0; oo < 4; ++oo) {
                accRe[jj][oo] += rR[jj]*p[jj][oo] - rI[jj]*q[jj][oo];
                accIm[jj][oo] += rI[jj]*p[jj][oo] + rR[jj]*q[jj][oo];
            }
    }

    // Combine the two halves: half 1 parks partials in smem (reuse w region)
    __syncthreads();
    float* buf = wrs;   // 8192 floats needed, 16384 available
    if (half == 1) {
#pragma unroll
        for (int jj = 0; jj < 4; ++jj) {
            *reinterpret_cast<float4*>(&buf[(tj*4+jj)*64 + to*4]) =
                make_float4(accRe[jj][0], accRe[jj][1], accRe[jj][2], accRe[jj][3]);
            *reinterpret_cast<float4*>(&buf[4096 + (tj*4+jj)*64 + to*4]) =
                make_float4(accIm[jj][0], accIm[jj][1], accIm[jj][2], accIm[jj][3]);
        }
    }
    __syncthreads();
    if (half == 0) {
        const int imag_off = BB*NN*OO;
#pragma unroll
        for (int jj = 0; jj < 4; ++jj) {
            float4 r2 = *reinterpret_cast<const float4*>(&buf[(tj*4+jj)*64 + to*4]);
            float4 i2 = *reinterpret_cast<const float4*>(&buf[4096 + (tj*4+jj)*64 + to*4]);
            int jg = jbase + tj*4 + jj;
            float4 re4 = make_float4(accRe[jj][0]+r2.x, accRe[jj][1]+r2.y,
                                     accRe[jj][2]+r2.z, accRe[jj][3]+r2.w);
            float4 im4 = make_float4(accIm[jj][0]+i2.x, accIm[jj][1]+i2.y,
                                     accIm[jj][2]+i2.z, accIm[jj][3]+i2.w);
            *reinterpret_cast<float4*>(out + (size_t)(b*NN + jg)*OO + to*4) = re4;
            *reinterpret_cast<float4*>(out + imag_off + (size_t)(b*NN + jg)*OO + to*4) = im4;
        }
    }
}

// ---------------------------------------------------------------------------
extern "C" void kernel_launch(void* const* d_in, const int* in_sizes, int n_in,
                              void* d_out, int out_size)
{
    const float* Xr  = (const float*)d_in[0];
    const float* Xi  = (const float*)d_in[1];
    const float* Lr  = (const float*)d_in[2];
    const float* Li  = (const float*)d_in[3];
    const float* wr  = (const float*)d_in[4];
    const float* wi  = (const float*)d_in[5];
    const float* awr = (const float*)d_in[6];
    const float* awi = (const float*)d_in[7];
    const float* abr = (const float*)d_in[8];
    const float* abi = (const float*)d_in[9];
    const float* par = (const float*)d_in[10];
    const float* pai = (const float*)d_in[11];
    float* out = (float*)d_out;

    // Idempotent, capture-safe (not a stream op); no static guard per harness rules.
    cudaFuncSetAttribute(k4_out, cudaFuncAttributeMaxDynamicSharedMemorySize,
                         K4_SMEM_BYTES);

    k1_svec  <<<BB*NN/8, 256>>>(Xr, Xi, awr, awi, abr, abi);
    k2_colsum<<<dim3(NN/32, BB), 256>>>(par, pai);
    k3_row   <<<BB*NN/8, 256>>>(Lr, Li, par, pai);
    k4_out   <<<dim3(NN/64, BB), 512, K4_SMEM_BYTES>>>(Xr, Xi, wr, wi, out);
}